// round 3
// baseline (speedup 1.0000x reference)
#include <cuda_runtime.h>
#include <cuda_bf16.h>
#include <cstdint>

#define N_NODES 100000
#define N_EDGES 1250000
#define D_IN 32
#define H 64
#define EPS 1e-5f

// scratch
__device__ float g_h[(size_t)N_NODES * H];     // hidden features
__device__ int   g_cnt[N_NODES];               // per-node in-degree
__device__ int   g_offs[N_NODES];              // CSR row starts (exclusive scan)
__device__ int   g_cursor[N_NODES];            // fill cursors
__device__ int   g_csr[N_EDGES];               // CSR column indices

// ---------------------------------------------------------------------------
// MLP: thread = node. x + h1 + h2 in registers, weights broadcast from shared
// via LDS.128. LN is thread-local (no shuffles, no cross-thread reduction).
// ---------------------------------------------------------------------------
__global__ __launch_bounds__(128)
void mlp_kernel(const float* __restrict__ x,
                const float* __restrict__ W1, const float* __restrict__ b1,
                const float* __restrict__ g1, const float* __restrict__ be1,
                const float* __restrict__ W2, const float* __restrict__ b2,
                const float* __restrict__ g2, const float* __restrict__ be2,
                float* __restrict__ h_out)
{
    __shared__ __align__(16) float sW1[D_IN * H];    // 8 KB
    __shared__ __align__(16) float sW2[H * H];       // 16 KB
    __shared__ __align__(16) float sbuf[128 * 36];   // 18 KB: x tile / h2 halves (stride 36)
    __shared__ float sb1[H], sg1[H], sbe1[H], sb2[H], sg2[H], sbe2[H];

    const int tid = threadIdx.x;
    const int B   = blockIdx.x * 128;   // first node of this block

    for (int i = tid; i < D_IN * H; i += 128) sW1[i] = W1[i];
    for (int i = tid; i < H * H;    i += 128) sW2[i] = W2[i];
    if (tid < H) {
        sb1[tid] = b1[tid]; sg1[tid] = g1[tid]; sbe1[tid] = be1[tid];
        sb2[tid] = b2[tid]; sg2[tid] = g2[tid]; sbe2[tid] = be2[tid];
    }

    // stage x tile coalesced into smem (stride 36 to dodge bank conflicts)
    for (int l = tid; l < 128 * D_IN; l += 128) {
        int n = l >> 5, k = l & 31;
        long long gidx = (long long)B * D_IN + l;
        sbuf[n * 36 + k] = (gidx < (long long)N_NODES * D_IN) ? x[gidx] : 0.f;
    }
    __syncthreads();

    // x into registers (8x LDS.128, 4-way conflict max)
    float xr[D_IN];
    #pragma unroll
    for (int c = 0; c < 8; c++) {
        float4 v = *reinterpret_cast<const float4*>(&sbuf[tid * 36 + c * 4]);
        xr[c*4+0] = v.x; xr[c*4+1] = v.y; xr[c*4+2] = v.z; xr[c*4+3] = v.w;
    }
    __syncthreads();   // sbuf will be reused for h2

    // ---- layer 1: 32 -> 64 ----
    float h1[H];
    #pragma unroll
    for (int j = 0; j < H; j++) h1[j] = sb1[j];
    #pragma unroll
    for (int k = 0; k < D_IN; k++) {
        float xk = xr[k];
        #pragma unroll
        for (int j4 = 0; j4 < 16; j4++) {
            float4 w = *reinterpret_cast<const float4*>(&sW1[k * H + j4 * 4]);
            h1[j4*4+0] = fmaf(xk, w.x, h1[j4*4+0]);
            h1[j4*4+1] = fmaf(xk, w.y, h1[j4*4+1]);
            h1[j4*4+2] = fmaf(xk, w.z, h1[j4*4+2]);
            h1[j4*4+3] = fmaf(xk, w.w, h1[j4*4+3]);
        }
    }
    // LN + ReLU (thread-local)
    {
        float s = 0.f, sq = 0.f;
        #pragma unroll
        for (int j = 0; j < H; j++) { s += h1[j]; sq = fmaf(h1[j], h1[j], sq); }
        float mu  = s * (1.f / H);
        float var = sq * (1.f / H) - mu * mu;
        float inv = rsqrtf(var + EPS);
        #pragma unroll
        for (int j = 0; j < H; j++)
            h1[j] = fmaxf(fmaf((h1[j] - mu) * inv, sg1[j], sbe1[j]), 0.f);
    }

    // ---- layer 2: 64 -> 64 ----
    float h2[H];
    #pragma unroll
    for (int j = 0; j < H; j++) h2[j] = sb2[j];
    #pragma unroll
    for (int k = 0; k < H; k++) {
        float hk = h1[k];
        #pragma unroll
        for (int j4 = 0; j4 < 16; j4++) {
            float4 w = *reinterpret_cast<const float4*>(&sW2[k * H + j4 * 4]);
            h2[j4*4+0] = fmaf(hk, w.x, h2[j4*4+0]);
            h2[j4*4+1] = fmaf(hk, w.y, h2[j4*4+1]);
            h2[j4*4+2] = fmaf(hk, w.z, h2[j4*4+2]);
            h2[j4*4+3] = fmaf(hk, w.w, h2[j4*4+3]);
        }
    }
    {
        float s = 0.f, sq = 0.f;
        #pragma unroll
        for (int j = 0; j < H; j++) { s += h2[j]; sq = fmaf(h2[j], h2[j], sq); }
        float mu  = s * (1.f / H);
        float var = sq * (1.f / H) - mu * mu;
        float inv = rsqrtf(var + EPS);
        #pragma unroll
        for (int j = 0; j < H; j++)
            h2[j] = fmaxf(fmaf((h2[j] - mu) * inv, sg2[j], sbe2[j]), 0.f);
    }

    // writeback via smem transpose, two 32-feature halves, coalesced STG
    #pragma unroll
    for (int half = 0; half < 2; half++) {
        #pragma unroll
        for (int c = 0; c < 8; c++) {
            float4 v = make_float4(h2[half*32 + c*4+0], h2[half*32 + c*4+1],
                                   h2[half*32 + c*4+2], h2[half*32 + c*4+3]);
            *reinterpret_cast<float4*>(&sbuf[tid * 36 + c * 4]) = v;
        }
        __syncthreads();
        for (int l = tid; l < 128 * 32; l += 128) {
            int n = l >> 5, j = l & 31;
            int node = B + n;
            if (node < N_NODES)
                h_out[(size_t)node * H + half * 32 + j] = sbuf[n * 36 + j];
        }
        __syncthreads();
    }
}

// ---------------------------------------------------------------------------
// CSR build: zero -> histogram -> scan -> fill
// ---------------------------------------------------------------------------
__global__ void zero_kernel(int* __restrict__ cnt)
{
    int i = blockIdx.x * blockDim.x + threadIdx.x;
    if (i < N_NODES) cnt[i] = 0;
}

__global__ __launch_bounds__(256)
void hist_kernel(const int* __restrict__ ei, int* __restrict__ cnt)
{
    int e = blockIdx.x * blockDim.x + threadIdx.x;
    if (e < N_EDGES) {
        int row = ei[e];
        atomicAdd(&cnt[row], 1);   // no return use -> REDG
    }
}

#define SCAN_T 1024
__global__ __launch_bounds__(SCAN_T)
void scan_kernel(const int* __restrict__ cnt, int* __restrict__ offs,
                 int* __restrict__ cursor)
{
    __shared__ int wsum[32];
    const int CHUNK = (N_NODES + SCAN_T - 1) / SCAN_T;   // 98
    int tid  = threadIdx.x;
    int lane = tid & 31, wid = tid >> 5;
    int base = tid * CHUNK;

    int s = 0;
    for (int i = 0; i < CHUNK; i++) {
        int idx = base + i;
        if (idx < N_NODES) s += cnt[idx];
    }
    // block exclusive scan of per-thread totals
    int incl = s;
    #pragma unroll
    for (int o = 1; o < 32; o <<= 1) {
        int v = __shfl_up_sync(0xFFFFFFFFu, incl, o);
        if (lane >= o) incl += v;
    }
    if (lane == 31) wsum[wid] = incl;
    __syncthreads();
    if (wid == 0) {
        int v = (lane < 32) ? wsum[lane] : 0;
        int wincl = v;
        #pragma unroll
        for (int o = 1; o < 32; o <<= 1) {
            int t = __shfl_up_sync(0xFFFFFFFFu, wincl, o);
            if (lane >= o) wincl += t;
        }
        wsum[lane] = wincl - v;   // exclusive
    }
    __syncthreads();
    int excl = incl - s + wsum[wid];

    int run = excl;
    for (int i = 0; i < CHUNK; i++) {
        int idx = base + i;
        if (idx < N_NODES) {
            offs[idx]   = run;
            cursor[idx] = run;
            run += cnt[idx];
        }
    }
}

__global__ __launch_bounds__(256)
void fill_kernel(const int* __restrict__ ei, int* __restrict__ cursor,
                 int* __restrict__ csr)
{
    int e = blockIdx.x * blockDim.x + threadIdx.x;
    if (e < N_EDGES) {
        int row = ei[e];
        int col = ei[N_EDGES + e];
        int p = atomicAdd(&cursor[row], 1);
        csr[p] = col;
    }
}

// ---------------------------------------------------------------------------
// Gather: warp per node. out[row] = h[row] + sum_{e in CSR(row)} h[col_e].
// 16 lanes per edge (one float4 slice each), 2 edges in flight per warp.
// ---------------------------------------------------------------------------
__global__ __launch_bounds__(256)
void gather_kernel(const int* __restrict__ offs, const int* __restrict__ cnt,
                   const int* __restrict__ csr, const float4* __restrict__ h4,
                   float4* __restrict__ out4)
{
    int warp = (blockIdx.x * blockDim.x + threadIdx.x) >> 5;
    if (warp >= N_NODES) return;
    int lane = threadIdx.x & 31;
    int sub  = lane >> 4;     // 0 or 1: which edge of the pair
    int f    = lane & 15;     // float4 slice 0..15

    int start = offs[warp];
    int deg   = cnt[warp];

    float4 acc = make_float4(0.f, 0.f, 0.f, 0.f);
    for (int i = sub; i < deg; i += 2) {
        int col = csr[start + i];
        float4 v = h4[(long long)col * 16 + f];
        acc.x += v.x; acc.y += v.y; acc.z += v.z; acc.w += v.w;
    }
    // merge the two sub-accumulators (lane f+16 -> lane f)
    acc.x += __shfl_down_sync(0xFFFFFFFFu, acc.x, 16);
    acc.y += __shfl_down_sync(0xFFFFFFFFu, acc.y, 16);
    acc.z += __shfl_down_sync(0xFFFFFFFFu, acc.z, 16);
    acc.w += __shfl_down_sync(0xFFFFFFFFu, acc.w, 16);

    if (lane < 16) {
        float4 own = h4[(long long)warp * 16 + lane];
        out4[(long long)warp * 16 + lane] =
            make_float4(own.x + acc.x, own.y + acc.y, own.z + acc.z, own.w + acc.w);
    }
}

// ---------------------------------------------------------------------------
extern "C" void kernel_launch(void* const* d_in, const int* in_sizes, int n_in,
                              void* d_out, int out_size)
{
    const float* x   = (const float*)d_in[0];
    const int*   ei  = (const int*)d_in[1];
    const float* W1  = (const float*)d_in[2];
    const float* b1  = (const float*)d_in[3];
    const float* g1  = (const float*)d_in[4];
    const float* be1 = (const float*)d_in[5];
    const float* W2  = (const float*)d_in[6];
    const float* b2  = (const float*)d_in[7];
    const float* g2  = (const float*)d_in[8];
    const float* be2 = (const float*)d_in[9];
    float* out = (float*)d_out;

    float *h_buf; int *cnt, *offs, *cursor, *csr;
    cudaGetSymbolAddress((void**)&h_buf,  g_h);
    cudaGetSymbolAddress((void**)&cnt,    g_cnt);
    cudaGetSymbolAddress((void**)&offs,   g_offs);
    cudaGetSymbolAddress((void**)&cursor, g_cursor);
    cudaGetSymbolAddress((void**)&csr,    g_csr);

    // CSR build
    zero_kernel<<<(N_NODES + 255) / 256, 256>>>(cnt);
    hist_kernel<<<(N_EDGES + 255) / 256, 256>>>(ei, cnt);
    scan_kernel<<<1, SCAN_T>>>(cnt, offs, cursor);
    fill_kernel<<<(N_EDGES + 255) / 256, 256>>>(ei, cursor, csr);

    // node MLP
    mlp_kernel<<<(N_NODES + 127) / 128, 128>>>(x, W1, b1, g1, be1,
                                               W2, b2, g2, be2, h_buf);

    // gather + residual
    gather_kernel<<<(N_NODES * 32 + 255) / 256, 256>>>(
        offs, cnt, csr, (const float4*)h_buf, (float4*)out);
}

// round 4
// speedup vs baseline: 1.9291x; 1.9291x over previous
#include <cuda_runtime.h>
#include <cuda_bf16.h>
#include <cstdint>

#define N_NODES 100000
#define N_EDGES 1250000
#define D_IN 32
#define H 64
#define EPS 1e-5f

// scratch for hidden features h [N_NODES, H]
__device__ float g_h[(size_t)N_NODES * H];

// ---------------------------------------------------------------------------
// MLP: thread = node. x + h1 + h2 in registers, weights broadcast from shared
// via LDS.128 (same address across warp -> conflict-free broadcast).
// LN is thread-local: no shuffles, no cross-thread reduction.
// Writes h to g_h AND initializes out = h (aggr red later).
// ---------------------------------------------------------------------------
__global__ __launch_bounds__(128)
void mlp_kernel(const float* __restrict__ x,
                const float* __restrict__ W1, const float* __restrict__ b1,
                const float* __restrict__ g1, const float* __restrict__ be1,
                const float* __restrict__ W2, const float* __restrict__ b2,
                const float* __restrict__ g2, const float* __restrict__ be2,
                float* __restrict__ h_out, float* __restrict__ out)
{
    __shared__ __align__(16) float sW1[D_IN * H];    // 8 KB
    __shared__ __align__(16) float sW2[H * H];       // 16 KB
    __shared__ __align__(16) float sbuf[128 * 36];   // 18 KB staging (stride 36)
    __shared__ float sb1[H], sg1[H], sbe1[H], sb2[H], sg2[H], sbe2[H];

    const int tid = threadIdx.x;
    const int B   = blockIdx.x * 128;   // first node of this block

    for (int i = tid; i < D_IN * H; i += 128) sW1[i] = W1[i];
    for (int i = tid; i < H * H;    i += 128) sW2[i] = W2[i];
    if (tid < H) {
        sb1[tid] = b1[tid]; sg1[tid] = g1[tid]; sbe1[tid] = be1[tid];
        sb2[tid] = b2[tid]; sg2[tid] = g2[tid]; sbe2[tid] = be2[tid];
    }

    // stage x tile coalesced into smem
    for (int l = tid; l < 128 * D_IN; l += 128) {
        int n = l >> 5, k = l & 31;
        long long gidx = (long long)B * D_IN + l;
        sbuf[n * 36 + k] = (gidx < (long long)N_NODES * D_IN) ? x[gidx] : 0.f;
    }
    __syncthreads();

    // x into registers (8x LDS.128)
    float xr[D_IN];
    #pragma unroll
    for (int c = 0; c < 8; c++) {
        float4 v = *reinterpret_cast<const float4*>(&sbuf[tid * 36 + c * 4]);
        xr[c*4+0] = v.x; xr[c*4+1] = v.y; xr[c*4+2] = v.z; xr[c*4+3] = v.w;
    }
    __syncthreads();   // sbuf reused for writeback

    // ---- layer 1: 32 -> 64 ----
    float h1[H];
    #pragma unroll
    for (int j = 0; j < H; j++) h1[j] = sb1[j];
    #pragma unroll
    for (int k = 0; k < D_IN; k++) {
        float xk = xr[k];
        #pragma unroll
        for (int j4 = 0; j4 < 16; j4++) {
            float4 w = *reinterpret_cast<const float4*>(&sW1[k * H + j4 * 4]);
            h1[j4*4+0] = fmaf(xk, w.x, h1[j4*4+0]);
            h1[j4*4+1] = fmaf(xk, w.y, h1[j4*4+1]);
            h1[j4*4+2] = fmaf(xk, w.z, h1[j4*4+2]);
            h1[j4*4+3] = fmaf(xk, w.w, h1[j4*4+3]);
        }
    }
    {   // LN + ReLU (thread-local)
        float s = 0.f, sq = 0.f;
        #pragma unroll
        for (int j = 0; j < H; j++) { s += h1[j]; sq = fmaf(h1[j], h1[j], sq); }
        float mu  = s * (1.f / H);
        float var = sq * (1.f / H) - mu * mu;
        float inv = rsqrtf(var + EPS);
        #pragma unroll
        for (int j = 0; j < H; j++)
            h1[j] = fmaxf(fmaf((h1[j] - mu) * inv, sg1[j], sbe1[j]), 0.f);
    }

    // ---- layer 2: 64 -> 64 ----
    float h2[H];
    #pragma unroll
    for (int j = 0; j < H; j++) h2[j] = sb2[j];
    #pragma unroll
    for (int k = 0; k < H; k++) {
        float hk = h1[k];
        #pragma unroll
        for (int j4 = 0; j4 < 16; j4++) {
            float4 w = *reinterpret_cast<const float4*>(&sW2[k * H + j4 * 4]);
            h2[j4*4+0] = fmaf(hk, w.x, h2[j4*4+0]);
            h2[j4*4+1] = fmaf(hk, w.y, h2[j4*4+1]);
            h2[j4*4+2] = fmaf(hk, w.z, h2[j4*4+2]);
            h2[j4*4+3] = fmaf(hk, w.w, h2[j4*4+3]);
        }
    }
    {
        float s = 0.f, sq = 0.f;
        #pragma unroll
        for (int j = 0; j < H; j++) { s += h2[j]; sq = fmaf(h2[j], h2[j], sq); }
        float mu  = s * (1.f / H);
        float var = sq * (1.f / H) - mu * mu;
        float inv = rsqrtf(var + EPS);
        #pragma unroll
        for (int j = 0; j < H; j++)
            h2[j] = fmaxf(fmaf((h2[j] - mu) * inv, sg2[j], sbe2[j]), 0.f);
    }

    // writeback via smem transpose, two 32-feature halves, coalesced STG
    #pragma unroll
    for (int half = 0; half < 2; half++) {
        #pragma unroll
        for (int c = 0; c < 8; c++) {
            *reinterpret_cast<float4*>(&sbuf[tid * 36 + c * 4]) =
                make_float4(h2[half*32 + c*4+0], h2[half*32 + c*4+1],
                            h2[half*32 + c*4+2], h2[half*32 + c*4+3]);
        }
        __syncthreads();
        for (int l = tid; l < 128 * 32; l += 128) {
            int n = l >> 5, j = l & 31;
            int node = B + n;
            if (node < N_NODES) {
                float v = sbuf[n * 36 + j];
                size_t o = (size_t)node * H + half * 32 + j;
                h_out[o] = v;
                out[o]   = v;   // init out = h
            }
        }
        __syncthreads();
    }
}

// ---------------------------------------------------------------------------
// Edge scatter: out[row] += h[col]. 16 threads/edge, float4 slices,
// red.global.add.v4.f32 (no-return reduction; REDG lane-throughput bound).
// ---------------------------------------------------------------------------
__global__ __launch_bounds__(256)
void edge_kernel(const int* __restrict__ ei,
                 const float4* __restrict__ h4,
                 float* __restrict__ out)
{
    long long idx = (long long)blockIdx.x * blockDim.x + threadIdx.x;
    int  lane16 = (int)(idx & 15);
    long long e = idx >> 4;
    if (e >= N_EDGES) return;

    int row = ei[e];            // destination
    int col = ei[N_EDGES + e];  // source
    if ((unsigned)row >= N_NODES || (unsigned)col >= N_NODES) return;

    float4 v = h4[(long long)col * 16 + lane16];
    float* p = out + (long long)row * H + lane16 * 4;
    asm volatile("red.global.add.v4.f32 [%0], {%1,%2,%3,%4};"
                 :: "l"(p), "f"(v.x), "f"(v.y), "f"(v.z), "f"(v.w)
                 : "memory");
}

// ---------------------------------------------------------------------------
extern "C" void kernel_launch(void* const* d_in, const int* in_sizes, int n_in,
                              void* d_out, int out_size)
{
    const float* x   = (const float*)d_in[0];
    const int*   ei  = (const int*)d_in[1];
    const float* W1  = (const float*)d_in[2];
    const float* b1  = (const float*)d_in[3];
    const float* g1  = (const float*)d_in[4];
    const float* be1 = (const float*)d_in[5];
    const float* W2  = (const float*)d_in[6];
    const float* b2  = (const float*)d_in[7];
    const float* g2  = (const float*)d_in[8];
    const float* be2 = (const float*)d_in[9];
    float* out = (float*)d_out;

    float* h_buf;
    cudaGetSymbolAddress((void**)&h_buf, g_h);

    // MLP + out init
    mlp_kernel<<<(N_NODES + 127) / 128, 128>>>(x, W1, b1, g1, be1,
                                               W2, b2, g2, be2, h_buf, out);

    // edge gather + vector scatter-add
    long long total = (long long)N_EDGES * 16;
    int blocks = (int)((total + 255) / 256);
    edge_kernel<<<blocks, 256>>>(ei, (const float4*)h_buf, out);
}

// round 5
// speedup vs baseline: 1.9528x; 1.0123x over previous
#include <cuda_runtime.h>
#include <cuda_bf16.h>
#include <cstdint>

#define N_NODES 100000
#define N_EDGES 1250000
#define D_IN 32
#define H 64
#define EPS 1e-5f

// scratch for hidden features h [N_NODES, H]
__device__ float g_h[(size_t)N_NODES * H];

// packed f32x2 helpers (Blackwell FFMA2 — only reachable via PTX)
__device__ __forceinline__ unsigned long long fma2(unsigned long long a,
                                                   unsigned long long b,
                                                   unsigned long long c)
{
    unsigned long long d;
    asm("fma.rn.f32x2 %0, %1, %2, %3;" : "=l"(d) : "l"(a), "l"(b), "l"(c));
    return d;
}
__device__ __forceinline__ unsigned long long pack2(float v)
{
    unsigned long long d;
    unsigned int u = __float_as_uint(v);
    asm("mov.b64 %0, {%1, %1};" : "=l"(d) : "r"(u));
    return d;
}
__device__ __forceinline__ void unpack2(unsigned long long v, float& lo, float& hi)
{
    unsigned int a, b;
    asm("mov.b64 {%0, %1}, %2;" : "=r"(a), "=r"(b) : "l"(v));
    lo = __uint_as_float(a); hi = __uint_as_float(b);
}

// ---------------------------------------------------------------------------
// MLP: thread = node. Accumulators as packed f32x2 (32 x b64), weights via
// broadcast LDS.128 (ulonglong2 = 2 packed pairs). LN thread-local.
// Writes h to g_h AND initializes out = h.
// ---------------------------------------------------------------------------
__global__ __launch_bounds__(128)
void mlp_kernel(const float* __restrict__ x,
                const float* __restrict__ W1, const float* __restrict__ b1,
                const float* __restrict__ g1, const float* __restrict__ be1,
                const float* __restrict__ W2, const float* __restrict__ b2,
                const float* __restrict__ g2, const float* __restrict__ be2,
                float* __restrict__ h_out, float* __restrict__ out)
{
    __shared__ __align__(16) float sW1[D_IN * H];    // 8 KB
    __shared__ __align__(16) float sW2[H * H];       // 16 KB
    __shared__ __align__(16) float sbuf[128 * 36];   // 18 KB staging (stride 36)
    __shared__ __align__(16) float sb1[H], sg1[H], sbe1[H], sb2[H], sg2[H], sbe2[H];

    const int tid = threadIdx.x;
    const int B   = blockIdx.x * 128;

    for (int i = tid; i < D_IN * H; i += 128) sW1[i] = W1[i];
    for (int i = tid; i < H * H;    i += 128) sW2[i] = W2[i];
    if (tid < H) {
        sb1[tid] = b1[tid]; sg1[tid] = g1[tid]; sbe1[tid] = be1[tid];
        sb2[tid] = b2[tid]; sg2[tid] = g2[tid]; sbe2[tid] = be2[tid];
    }

    // stage x tile coalesced into smem
    for (int l = tid; l < 128 * D_IN; l += 128) {
        int n = l >> 5, k = l & 31;
        long long gidx = (long long)B * D_IN + l;
        sbuf[n * 36 + k] = (gidx < (long long)N_NODES * D_IN) ? x[gidx] : 0.f;
    }
    __syncthreads();

    // x into registers
    float xr[D_IN];
    #pragma unroll
    for (int c = 0; c < 8; c++) {
        float4 v = *reinterpret_cast<const float4*>(&sbuf[tid * 36 + c * 4]);
        xr[c*4+0] = v.x; xr[c*4+1] = v.y; xr[c*4+2] = v.z; xr[c*4+3] = v.w;
    }
    __syncthreads();   // sbuf reused for writeback

    // ---- layer 1: 32 -> 64  (packed f32x2 accumulators) ----
    unsigned long long acc[H / 2];
    #pragma unroll
    for (int j2 = 0; j2 < H / 2; j2++)
        acc[j2] = reinterpret_cast<const unsigned long long*>(sb1)[j2];

    #pragma unroll 8
    for (int k = 0; k < D_IN; k++) {
        unsigned long long xk2 = pack2(xr[k]);
        const ulonglong2* wrow = reinterpret_cast<const ulonglong2*>(&sW1[k * H]);
        #pragma unroll
        for (int j4 = 0; j4 < 16; j4++) {
            ulonglong2 w = wrow[j4];
            acc[j4*2+0] = fma2(xk2, w.x, acc[j4*2+0]);
            acc[j4*2+1] = fma2(xk2, w.y, acc[j4*2+1]);
        }
    }

    // LN + ReLU (thread-local, scalar)
    float h1[H];
    #pragma unroll
    for (int j2 = 0; j2 < H / 2; j2++) unpack2(acc[j2], h1[j2*2], h1[j2*2+1]);
    {
        float s = 0.f, sq = 0.f;
        #pragma unroll
        for (int j = 0; j < H; j++) { s += h1[j]; sq = fmaf(h1[j], h1[j], sq); }
        float mu  = s * (1.f / H);
        float var = sq * (1.f / H) - mu * mu;
        float inv = rsqrtf(var + EPS);
        #pragma unroll
        for (int j = 0; j < H; j++)
            h1[j] = fmaxf(fmaf((h1[j] - mu) * inv, sg1[j], sbe1[j]), 0.f);
    }

    // ---- layer 2: 64 -> 64 ----
    #pragma unroll
    for (int j2 = 0; j2 < H / 2; j2++)
        acc[j2] = reinterpret_cast<const unsigned long long*>(sb2)[j2];

    #pragma unroll 8
    for (int k = 0; k < H; k++) {
        unsigned long long hk2 = pack2(h1[k]);
        const ulonglong2* wrow = reinterpret_cast<const ulonglong2*>(&sW2[k * H]);
        #pragma unroll
        for (int j4 = 0; j4 < 16; j4++) {
            ulonglong2 w = wrow[j4];
            acc[j4*2+0] = fma2(hk2, w.x, acc[j4*2+0]);
            acc[j4*2+1] = fma2(hk2, w.y, acc[j4*2+1]);
        }
    }

    float h2[H];
    #pragma unroll
    for (int j2 = 0; j2 < H / 2; j2++) unpack2(acc[j2], h2[j2*2], h2[j2*2+1]);
    {
        float s = 0.f, sq = 0.f;
        #pragma unroll
        for (int j = 0; j < H; j++) { s += h2[j]; sq = fmaf(h2[j], h2[j], sq); }
        float mu  = s * (1.f / H);
        float var = sq * (1.f / H) - mu * mu;
        float inv = rsqrtf(var + EPS);
        #pragma unroll
        for (int j = 0; j < H; j++)
            h2[j] = fmaxf(fmaf((h2[j] - mu) * inv, sg2[j], sbe2[j]), 0.f);
    }

    // writeback via smem transpose, two 32-feature halves, coalesced STG
    #pragma unroll
    for (int half = 0; half < 2; half++) {
        #pragma unroll
        for (int c = 0; c < 8; c++) {
            *reinterpret_cast<float4*>(&sbuf[tid * 36 + c * 4]) =
                make_float4(h2[half*32 + c*4+0], h2[half*32 + c*4+1],
                            h2[half*32 + c*4+2], h2[half*32 + c*4+3]);
        }
        __syncthreads();
        for (int l = tid; l < 128 * 32; l += 128) {
            int n = l >> 5, j = l & 31;
            int node = B + n;
            if (node < N_NODES) {
                float v = sbuf[n * 36 + j];
                size_t o = (size_t)node * H + half * 32 + j;
                h_out[o] = v;
                out[o]   = v;   // init out = h
            }
        }
        __syncthreads();
    }
}

// ---------------------------------------------------------------------------
// Edge scatter: out[row] += h[col]. 16 threads/edge, red.global.add.v4.f32.
// Measured at REDG lane-throughput floor — do not touch.
// ---------------------------------------------------------------------------
__global__ __launch_bounds__(256)
void edge_kernel(const int* __restrict__ ei,
                 const float4* __restrict__ h4,
                 float* __restrict__ out)
{
    long long idx = (long long)blockIdx.x * blockDim.x + threadIdx.x;
    int  lane16 = (int)(idx & 15);
    long long e = idx >> 4;
    if (e >= N_EDGES) return;

    int row = ei[e];            // destination
    int col = ei[N_EDGES + e];  // source
    if ((unsigned)row >= N_NODES || (unsigned)col >= N_NODES) return;

    float4 v = h4[(long long)col * 16 + lane16];
    float* p = out + (long long)row * H + lane16 * 4;
    asm volatile("red.global.add.v4.f32 [%0], {%1,%2,%3,%4};"
                 :: "l"(p), "f"(v.x), "f"(v.y), "f"(v.z), "f"(v.w)
                 : "memory");
}

// ---------------------------------------------------------------------------
extern "C" void kernel_launch(void* const* d_in, const int* in_sizes, int n_in,
                              void* d_out, int out_size)
{
    const float* x   = (const float*)d_in[0];
    const int*   ei  = (const int*)d_in[1];
    const float* W1  = (const float*)d_in[2];
    const float* b1  = (const float*)d_in[3];
    const float* g1  = (const float*)d_in[4];
    const float* be1 = (const float*)d_in[5];
    const float* W2  = (const float*)d_in[6];
    const float* b2  = (const float*)d_in[7];
    const float* g2  = (const float*)d_in[8];
    const float* be2 = (const float*)d_in[9];
    float* out = (float*)d_out;

    float* h_buf;
    cudaGetSymbolAddress((void**)&h_buf, g_h);

    mlp_kernel<<<(N_NODES + 127) / 128, 128>>>(x, W1, b1, g1, be1,
                                               W2, b2, g2, be2, h_buf, out);

    long long total = (long long)N_EDGES * 16;
    int blocks = (int)((total + 255) / 256);
    edge_kernel<<<blocks, 256>>>(ei, (const float4*)h_buf, out);
}

// round 6
// speedup vs baseline: 2.0673x; 1.0586x over previous
#include <cuda_runtime.h>
#include <cuda_bf16.h>
#include <cstdint>

#define N_NODES 100000
#define N_EDGES 1250000
#define D_IN 32
#define H 64
#define EPS 1e-5f

// scratch for hidden features h [N_NODES, H]
__device__ float g_h[(size_t)N_NODES * H];

// packed f32x2 helpers (Blackwell FFMA2 — only reachable via PTX)
__device__ __forceinline__ unsigned long long fma2(unsigned long long a,
                                                   unsigned long long b,
                                                   unsigned long long c)
{
    unsigned long long d;
    asm("fma.rn.f32x2 %0, %1, %2, %3;" : "=l"(d) : "l"(a), "l"(b), "l"(c));
    return d;
}
__device__ __forceinline__ unsigned long long pack2(float v)
{
    unsigned long long d;
    unsigned int u = __float_as_uint(v);
    asm("mov.b64 %0, {%1, %1};" : "=l"(d) : "r"(u));
    return d;
}
__device__ __forceinline__ void unpack2(unsigned long long v, float& lo, float& hi)
{
    unsigned int a, b;
    asm("mov.b64 {%0, %1}, %2;" : "=r"(a), "=r"(b) : "l"(v));
    lo = __uint_as_float(a); hi = __uint_as_float(b);
}

// ---------------------------------------------------------------------------
// MLP: thread = node. Packed f32x2 accumulators, weights via broadcast
// LDS.128, x read per-k from conflict-free smem (stride 33). Register-capped
// to 128 (4 blocks/SM) — occupancy is the lever this round.
// Writes h to g_h AND initializes out = h.
// ---------------------------------------------------------------------------
__global__ __launch_bounds__(128, 4)
void mlp_kernel(const float* __restrict__ x,
                const float* __restrict__ W1, const float* __restrict__ b1,
                const float* __restrict__ g1, const float* __restrict__ be1,
                const float* __restrict__ W2, const float* __restrict__ b2,
                const float* __restrict__ g2, const float* __restrict__ be2,
                float* __restrict__ h_out, float* __restrict__ out)
{
    __shared__ __align__(16) float sW1[D_IN * H];    // 8 KB
    __shared__ __align__(16) float sW2[H * H];       // 16 KB
    __shared__ __align__(16) float sx[128 * 33];     // 16.5 KB x / staging (stride 33)
    __shared__ __align__(16) float sb1[H], sg1[H], sbe1[H], sb2[H], sg2[H], sbe2[H];

    const int tid = threadIdx.x;
    const int B   = blockIdx.x * 128;

    for (int i = tid; i < D_IN * H; i += 128) sW1[i] = W1[i];
    for (int i = tid; i < H * H;    i += 128) sW2[i] = W2[i];
    if (tid < H) {
        sb1[tid] = b1[tid]; sg1[tid] = g1[tid]; sbe1[tid] = be1[tid];
        sb2[tid] = b2[tid]; sg2[tid] = g2[tid]; sbe2[tid] = be2[tid];
    }

    // stage x tile coalesced into smem (stride 33: bank = t + k, conflict-free)
    for (int l = tid; l < 128 * D_IN; l += 128) {
        int n = l >> 5, k = l & 31;
        long long gidx = (long long)B * D_IN + l;
        sx[n * 33 + k] = (gidx < (long long)N_NODES * D_IN) ? x[gidx] : 0.f;
    }
    __syncthreads();

    // ---- layer 1: 32 -> 64  (packed f32x2 accumulators) ----
    unsigned long long acc[H / 2];
    #pragma unroll
    for (int j2 = 0; j2 < H / 2; j2++)
        acc[j2] = reinterpret_cast<const unsigned long long*>(sb1)[j2];

    #pragma unroll 8
    for (int k = 0; k < D_IN; k++) {
        unsigned long long xk2 = pack2(sx[tid * 33 + k]);   // scalar LDS, no conflict
        const ulonglong2* wrow = reinterpret_cast<const ulonglong2*>(&sW1[k * H]);
        #pragma unroll
        for (int j4 = 0; j4 < 16; j4++) {
            ulonglong2 w = wrow[j4];
            acc[j4*2+0] = fma2(xk2, w.x, acc[j4*2+0]);
            acc[j4*2+1] = fma2(xk2, w.y, acc[j4*2+1]);
        }
    }

    // LN + ReLU (thread-local)
    float h1[H];
    #pragma unroll
    for (int j2 = 0; j2 < H / 2; j2++) unpack2(acc[j2], h1[j2*2], h1[j2*2+1]);
    {
        float s = 0.f, sq = 0.f;
        #pragma unroll
        for (int j = 0; j < H; j++) { s += h1[j]; sq = fmaf(h1[j], h1[j], sq); }
        float mu  = s * (1.f / H);
        float var = sq * (1.f / H) - mu * mu;
        float inv = rsqrtf(var + EPS);
        #pragma unroll
        for (int j = 0; j < H; j++)
            h1[j] = fmaxf(fmaf((h1[j] - mu) * inv, sg1[j], sbe1[j]), 0.f);
    }

    // ---- layer 2: 64 -> 64 ----
    #pragma unroll
    for (int j2 = 0; j2 < H / 2; j2++)
        acc[j2] = reinterpret_cast<const unsigned long long*>(sb2)[j2];

    #pragma unroll 8
    for (int k = 0; k < H; k++) {
        unsigned long long hk2 = pack2(h1[k]);
        const ulonglong2* wrow = reinterpret_cast<const ulonglong2*>(&sW2[k * H]);
        #pragma unroll
        for (int j4 = 0; j4 < 16; j4++) {
            ulonglong2 w = wrow[j4];
            acc[j4*2+0] = fma2(hk2, w.x, acc[j4*2+0]);
            acc[j4*2+1] = fma2(hk2, w.y, acc[j4*2+1]);
        }
    }

    float h2[H];
    #pragma unroll
    for (int j2 = 0; j2 < H / 2; j2++) unpack2(acc[j2], h2[j2*2], h2[j2*2+1]);
    {
        float s = 0.f, sq = 0.f;
        #pragma unroll
        for (int j = 0; j < H; j++) { s += h2[j]; sq = fmaf(h2[j], h2[j], sq); }
        float mu  = s * (1.f / H);
        float var = sq * (1.f / H) - mu * mu;
        float inv = rsqrtf(var + EPS);
        #pragma unroll
        for (int j = 0; j < H; j++)
            h2[j] = fmaxf(fmaf((h2[j] - mu) * inv, sg2[j], sbe2[j]), 0.f);
    }

    // writeback via smem transpose (stride 33, scalar STS conflict-free),
    // two 32-feature halves, coalesced STG
    #pragma unroll
    for (int half = 0; half < 2; half++) {
        __syncthreads();   // protect sx from previous use
        #pragma unroll
        for (int c = 0; c < 32; c++)
            sx[tid * 33 + c] = h2[half * 32 + c];
        __syncthreads();
        for (int l = tid; l < 128 * 32; l += 128) {
            int n = l >> 5, j = l & 31;
            int node = B + n;
            if (node < N_NODES) {
                float v = sx[n * 33 + j];
                size_t o = (size_t)node * H + half * 32 + j;
                h_out[o] = v;
                out[o]   = v;   // init out = h
            }
        }
    }
}

// ---------------------------------------------------------------------------
// Edge scatter: out[row] += h[col]. 16 threads/edge, red.global.add.v4.f32.
// Measured at REDG lane-throughput floor across 3 rounds — do not touch.
// ---------------------------------------------------------------------------
__global__ __launch_bounds__(256)
void edge_kernel(const int* __restrict__ ei,
                 const float4* __restrict__ h4,
                 float* __restrict__ out)
{
    long long idx = (long long)blockIdx.x * blockDim.x + threadIdx.x;
    int  lane16 = (int)(idx & 15);
    long long e = idx >> 4;
    if (e >= N_EDGES) return;

    int row = ei[e];            // destination
    int col = ei[N_EDGES + e];  // source
    if ((unsigned)row >= N_NODES || (unsigned)col >= N_NODES) return;

    float4 v = h4[(long long)col * 16 + lane16];
    float* p = out + (long long)row * H + lane16 * 4;
    asm volatile("red.global.add.v4.f32 [%0], {%1,%2,%3,%4};"
                 :: "l"(p), "f"(v.x), "f"(v.y), "f"(v.z), "f"(v.w)
                 : "memory");
}

// ---------------------------------------------------------------------------
extern "C" void kernel_launch(void* const* d_in, const int* in_sizes, int n_in,
                              void* d_out, int out_size)
{
    const float* x   = (const float*)d_in[0];
    const int*   ei  = (const int*)d_in[1];
    const float* W1  = (const float*)d_in[2];
    const float* b1  = (const float*)d_in[3];
    const float* g1  = (const float*)d_in[4];
    const float* be1 = (const float*)d_in[5];
    const float* W2  = (const float*)d_in[6];
    const float* b2  = (const float*)d_in[7];
    const float* g2  = (const float*)d_in[8];
    const float* be2 = (const float*)d_in[9];
    float* out = (float*)d_out;

    float* h_buf;
    cudaGetSymbolAddress((void**)&h_buf, g_h);

    mlp_kernel<<<(N_NODES + 127) / 128, 128>>>(x, W1, b1, g1, be1,
                                               W2, b2, g2, be2, h_buf, out);

    long long total = (long long)N_EDGES * 16;
    int blocks = (int)((total + 255) / 256);
    edge_kernel<<<blocks, 256>>>(ei, (const float4*)h_buf, out);
}